// round 12
// baseline (speedup 1.0000x reference)
#include <cuda_runtime.h>

// x_ref, x : [B=4, C=3, H=512, W=512] float32
// out: [4,3,512,512] f32 (3145728) then best_shifts [4,2] as floats (8)

#define NIMG   12
#define HH     512
#define WW     512
#define W4     (WW/4)
#define PROWS  520          // 4-row halo each side
#define PADW   520          // 4-col halo each side
#define PADW4  (PADW/4)     // 130
#define NSHIFT 81
#define IMG_ELEMS (HH*WW)
#define OUT_IMG   (NIMG*IMG_ELEMS)
#define NBLK   768          // 12 imgs * 64 blocks (8 rows per block)
#define BLK_PER_BATCH 192   // 3 imgs * 64

__device__ float4 g_refpad[NIMG * PROWS * PADW4];   // ~13 MB zero-padded ref
__device__ float  g_partial[NBLK * NSHIFT];
__device__ int2   g_best[4];

// ---------------------------------------------------------------------------
// Phase 0: zero-padded ref copy, one aligned float4 per thread (DRAM-bound).
// ---------------------------------------------------------------------------
__global__ void __launch_bounds__(256) prep_kernel(const float* __restrict__ xref) {
    int idx = blockIdx.x * 256 + threadIdx.x;
    const int total4 = NIMG * PROWS * PADW4;     // 811200
    if (idx >= total4) return;
    int pc4 = idx % PADW4;
    int pr  = (idx / PADW4) % PROWS;
    int img = idx / (PADW4 * PROWS);
    int srow = pr - 4;
    float4 v = make_float4(0.f, 0.f, 0.f, 0.f);
    if ((unsigned)srow < (unsigned)HH && pc4 >= 1 && pc4 <= 128) {
        v = __ldg((const float4*)(xref + ((size_t)img * HH + srow) * WW) + (pc4 - 1));
    }
    g_refpad[idx] = v;
}

// ---------------------------------------------------------------------------
// Phase 1: 81-shift correlation on the padded ref (branch-free hot loop).
// Thread: 2 rows x 8 cols; dx-outer; 9 live accumulators; 1296 FMAs/thread.
// ~55 live regs -> fits default 64-reg allocation, NO spills, 32 warps/SM.
// Block = 256 thr = 4 rowgroups(2 rows) x 64 strips; covers 8 image rows.
// ---------------------------------------------------------------------------
__global__ void __launch_bounds__(256) corr_kernel(const float* __restrict__ x) {
    __shared__ float ssum[NSHIFT];
    if (threadIdx.x < NSHIFT) ssum[threadIdx.x] = 0.0f;
    __syncthreads();

    int img    = blockIdx.x >> 6;             // 64 blocks per image
    int rowblk = blockIdx.x & 63;
    int strip  = threadIdx.x & 63;
    int rgrp   = threadIdx.x >> 6;            // 0..3
    int a0     = rowblk * 8 + rgrp * 2;       // first of 2 image rows
    int lane   = threadIdx.x & 31;

    // preload x strip: 2 rows x 8 cols (16 regs)
    const float4* xp4 = (const float4*)x + (size_t)img * HH * W4;
    float xv[16];
#pragma unroll
    for (int r = 0; r < 2; r++) {
        float4 m0 = __ldg(xp4 + (a0 + r) * W4 + strip * 2);
        float4 m1 = __ldg(xp4 + (a0 + r) * W4 + strip * 2 + 1);
        xv[r * 8 + 0] = m0.x; xv[r * 8 + 1] = m0.y;
        xv[r * 8 + 2] = m0.z; xv[r * 8 + 3] = m0.w;
        xv[r * 8 + 4] = m1.x; xv[r * 8 + 5] = m1.y;
        xv[r * 8 + 6] = m1.z; xv[r * 8 + 7] = m1.w;
    }

    // running row pointer: (dx=0, r=0) touches padded row a0, padded col j0
    const float4* rrow = g_refpad + (size_t)img * PROWS * PADW4
                         + (size_t)a0 * PADW4 + strip * 2;

#pragma unroll 1
    for (int dx = 0; dx < 9; dx++) {
        float acc[9];
#pragma unroll
        for (int d = 0; d < 9; d++) acc[d] = 0.0f;

#pragma unroll
        for (int r = 0; r < 2; r++) {
            const float4* rp = rrow + r * PADW4;
            float4 q0 = rp[0], q1 = rp[1], q2 = rp[2], q3 = rp[3];
            float rv[16] = {q0.x, q0.y, q0.z, q0.w, q1.x, q1.y, q1.z, q1.w,
                            q2.x, q2.y, q2.z, q2.w, q3.x, q3.y, q3.z, q3.w};
#pragma unroll
            for (int p = 0; p < 8; p++) {
#pragma unroll
                for (int d = 0; d < 9; d++) {
                    acc[d] += xv[r * 8 + p] * rv[p + d];
                }
            }
        }

        // warp butterfly per dy, then one-lane atomic into block smem
#pragma unroll
        for (int d = 0; d < 9; d++) {
            float v = acc[d];
            v += __shfl_xor_sync(0xffffffffu, v, 16);
            v += __shfl_xor_sync(0xffffffffu, v, 8);
            v += __shfl_xor_sync(0xffffffffu, v, 4);
            v += __shfl_xor_sync(0xffffffffu, v, 2);
            v += __shfl_xor_sync(0xffffffffu, v, 1);
            int s = dx * 9 + d;
            if (lane == (s & 31)) atomicAdd(&ssum[s], v);
        }
        rrow += PADW4;
    }

    __syncthreads();
    if (threadIdx.x < NSHIFT)
        g_partial[blockIdx.x * NSHIFT + threadIdx.x] = ssum[threadIdx.x];
}

// ---------------------------------------------------------------------------
// Phase 2: deterministic reduce of 192 partials per (batch,shift) + argmax
// (first-max tie-break, matching jnp.argmax).
// ---------------------------------------------------------------------------
__global__ void __launch_bounds__(384) reduce_argmax_kernel(float* __restrict__ d_out,
                                                            int out_size) {
    __shared__ float sims[4 * NSHIFT];
    int t = threadIdx.x;
    if (t < 4 * NSHIFT) {
        int b = t / NSHIFT;
        int s = t - b * NSHIFT;
        const float* pp = g_partial + (size_t)b * BLK_PER_BATCH * NSHIFT + s;
        float acc = 0.0f;
#pragma unroll 8
        for (int i = 0; i < BLK_PER_BATCH; i++) acc += pp[i * NSHIFT];
        sims[t] = acc;
    }
    __syncthreads();

    int w = t >> 5, lane = t & 31;
    if (w < 4) {
        float bv = -3.0e38f;
        int bi = NSHIFT;
        for (int s = lane; s < NSHIFT; s += 32) {
            float v = sims[w * NSHIFT + s];
            if (v > bv || (v == bv && s < bi)) { bv = v; bi = s; }
        }
#pragma unroll
        for (int off = 16; off; off >>= 1) {
            float ov = __shfl_xor_sync(0xffffffffu, bv, off);
            int   oi = __shfl_xor_sync(0xffffffffu, bi, off);
            if (ov > bv || (ov == bv && oi < bi)) { bv = ov; bi = oi; }
        }
        if (lane == 0) {
            int sx = bi / 9 - 4;
            int sy = bi % 9 - 4;
            g_best[w] = make_int2(sx, sy);
            if (out_size >= OUT_IMG + 8) {
                d_out[OUT_IMG + w * 2 + 0] = (float)sx;
                d_out[OUT_IMG + w * 2 + 1] = (float)sy;
            }
        }
    }
}

// ---------------------------------------------------------------------------
// Phase 3: apply best shift. 8 floats per thread: 3 aligned LDG.128 +
// warp-uniform extract -> 2 STG.128.
// ---------------------------------------------------------------------------
__global__ void __launch_bounds__(256) apply_kernel(const float* __restrict__ x,
                                                    float* __restrict__ out) {
    int t = blockIdx.x * 256 + threadIdx.x;
    int base = t << 3;                     // 8 floats per thread
    int j0  = base & 511;                  // multiple of 8
    int i   = (base >> 9) & 511;
    int img = base >> 18;
    int b   = img / 3;
    int2 s  = g_best[b];
    int si  = i - s.x;

    const float4 z4 = make_float4(0.f, 0.f, 0.f, 0.f);
    float4 o0 = z4, o1 = z4;

    if ((unsigned)si < (unsigned)HH) {
        int sj0 = j0 - s.y;
        int sa  = sj0 & ~3;
        int off = sj0 & 3;                 // warp-uniform
        const float* row = x + ((size_t)img << 18) + (si << 9);
        float4 q0 = ((unsigned)sa       < (unsigned)WW) ? __ldg((const float4*)(row + sa))     : z4;
        float4 q1 = ((unsigned)(sa + 4) < (unsigned)WW) ? __ldg((const float4*)(row + sa + 4)) : z4;
        float4 q2 = ((unsigned)(sa + 8) < (unsigned)WW) ? __ldg((const float4*)(row + sa + 8)) : z4;
        switch (off) {
            case 0:
                o0 = q0; o1 = q1;
                break;
            case 1:
                o0 = make_float4(q0.y, q0.z, q0.w, q1.x);
                o1 = make_float4(q1.y, q1.z, q1.w, q2.x);
                break;
            case 2:
                o0 = make_float4(q0.z, q0.w, q1.x, q1.y);
                o1 = make_float4(q1.z, q1.w, q2.x, q2.y);
                break;
            default:
                o0 = make_float4(q0.w, q1.x, q1.y, q1.z);
                o1 = make_float4(q1.w, q2.x, q2.y, q2.z);
                break;
        }
    }
    float4* op = (float4*)out + (t << 1);
    op[0] = o0; op[1] = o1;
}

// ---------------------------------------------------------------------------
extern "C" void kernel_launch(void* const* d_in, const int* in_sizes, int n_in,
                              void* d_out, int out_size) {
    const float* x_ref = (const float*)d_in[0];
    const float* x     = (const float*)d_in[1];
    float* out = (float*)d_out;

    {
        int total4 = NIMG * PROWS * PADW4;
        prep_kernel<<<(total4 + 255) / 256, 256>>>(x_ref);
    }
    corr_kernel<<<NBLK, 256>>>(x);
    reduce_argmax_kernel<<<1, 384>>>(out, out_size);
    apply_kernel<<<OUT_IMG / 8 / 256, 256>>>(x, out);
}

// round 13
// speedup vs baseline: 1.4214x; 1.4214x over previous
#include <cuda_runtime.h>

// x_ref, x : [B=4, C=3, H=512, W=512] float32
// out: [4,3,512,512] f32 (3145728) then best_shifts [4,2] as floats (8)

#define NIMG   12
#define HH     512
#define WW     512
#define W4     (WW/4)
#define PROWS  520          // 4-row halo each side
#define PADW   520          // 4-col halo each side
#define PADW4  (PADW/4)     // 130
#define NSHIFT 81
#define IMG_ELEMS (HH*WW)
#define OUT_IMG   (NIMG*IMG_ELEMS)
#define NBLK   384          // 12 imgs * 32 blocks
#define BLK_PER_BATCH 96    // 3 imgs * 32

__device__ float4 g_refpad[NIMG * PROWS * PADW4];   // ~13 MB zero-padded ref
__device__ float  g_partial[NBLK * NSHIFT];
__device__ int2   g_best[4];

// ---------------------------------------------------------------------------
// Phase 0: zero-padded ref copy, one aligned float4 per thread (DRAM-bound).
// ---------------------------------------------------------------------------
__global__ void __launch_bounds__(256) prep_kernel(const float* __restrict__ xref) {
    int idx = blockIdx.x * 256 + threadIdx.x;
    const int total4 = NIMG * PROWS * PADW4;     // 811200
    if (idx >= total4) return;
    int pc4 = idx % PADW4;
    int pr  = (idx / PADW4) % PROWS;
    int img = idx / (PADW4 * PROWS);
    int srow = pr - 4;
    float4 v = make_float4(0.f, 0.f, 0.f, 0.f);
    if ((unsigned)srow < (unsigned)HH && pc4 >= 1 && pc4 <= 128) {
        v = __ldg((const float4*)(xref + ((size_t)img * HH + srow) * WW) + (pc4 - 1));
    }
    g_refpad[idx] = v;
}

// ---------------------------------------------------------------------------
// Phase 1: 81-shift correlation on the padded ref (branch-free hot loop).
// Thread: 4 rows x 8 cols; dx-outer; 9 live accumulators; 2592 FMAs/thread.
// Inner loop iterates over REF elements (k = p+d): each ref float4 is
// consumed immediately -> no rv[16] window buffer -> ~56 live regs, fits
// the default 64-reg allocation with NO spills.
// Block = 256 thr = 4 rowgroups x 64 strips; 32 blocks per image.
// ---------------------------------------------------------------------------
__global__ void __launch_bounds__(256) corr_kernel(const float* __restrict__ x) {
    __shared__ float ssum[NSHIFT];
    if (threadIdx.x < NSHIFT) ssum[threadIdx.x] = 0.0f;
    __syncthreads();

    int img   = blockIdx.x >> 5;
    int strip = threadIdx.x & 63;
    int rgrp  = ((blockIdx.x & 31) << 2) + (threadIdx.x >> 6);
    int a0    = rgrp * 4;
    int lane  = threadIdx.x & 31;

    // preload x strip: 4 rows x 8 cols (32 regs)
    const float4* xp4 = (const float4*)x + (size_t)img * HH * W4;
    float xv[32];
#pragma unroll
    for (int r = 0; r < 4; r++) {
        float4 m0 = __ldg(xp4 + (a0 + r) * W4 + strip * 2);
        float4 m1 = __ldg(xp4 + (a0 + r) * W4 + strip * 2 + 1);
        xv[r * 8 + 0] = m0.x; xv[r * 8 + 1] = m0.y;
        xv[r * 8 + 2] = m0.z; xv[r * 8 + 3] = m0.w;
        xv[r * 8 + 4] = m1.x; xv[r * 8 + 5] = m1.y;
        xv[r * 8 + 6] = m1.z; xv[r * 8 + 7] = m1.w;
    }

    // running row pointer: (dx=0, r=0) touches padded row a0, padded col 8*strip
    const float4* rrow = g_refpad + (size_t)img * PROWS * PADW4
                         + (size_t)a0 * PADW4 + strip * 2;

#pragma unroll 1
    for (int dx = 0; dx < 9; dx++) {
        float acc[9];
#pragma unroll
        for (int d = 0; d < 9; d++) acc[d] = 0.0f;

#pragma unroll
        for (int r = 0; r < 4; r++) {
            const float4* rp = rrow + r * PADW4;
#pragma unroll
            for (int g = 0; g < 4; g++) {
                float4 q = rp[g];
                float qq[4] = {q.x, q.y, q.z, q.w};
#pragma unroll
                for (int u = 0; u < 4; u++) {
                    const int k   = g * 4 + u;           // ref window index 0..15
                    const int dlo = (k - 7 < 0) ? 0 : k - 7;
                    const int dhi = (k < 8) ? k : 8;
#pragma unroll
                    for (int d = dlo; d <= dhi; d++) {
                        acc[d] += xv[r * 8 + (k - d)] * qq[u];
                    }
                }
            }
        }

        // warp butterfly per dy, then one-lane atomic into block smem
#pragma unroll
        for (int d = 0; d < 9; d++) {
            float v = acc[d];
            v += __shfl_xor_sync(0xffffffffu, v, 16);
            v += __shfl_xor_sync(0xffffffffu, v, 8);
            v += __shfl_xor_sync(0xffffffffu, v, 4);
            v += __shfl_xor_sync(0xffffffffu, v, 2);
            v += __shfl_xor_sync(0xffffffffu, v, 1);
            int s = dx * 9 + d;
            if (lane == (s & 31)) atomicAdd(&ssum[s], v);
        }
        rrow += PADW4;
    }

    __syncthreads();
    if (threadIdx.x < NSHIFT)
        g_partial[blockIdx.x * NSHIFT + threadIdx.x] = ssum[threadIdx.x];
}

// ---------------------------------------------------------------------------
// Phase 2: deterministic reduce of 96 partials per (batch,shift) + argmax
// (first-max tie-break, matching jnp.argmax).
// ---------------------------------------------------------------------------
__global__ void __launch_bounds__(384) reduce_argmax_kernel(float* __restrict__ d_out,
                                                            int out_size) {
    __shared__ float sims[4 * NSHIFT];
    int t = threadIdx.x;
    if (t < 4 * NSHIFT) {
        int b = t / NSHIFT;
        int s = t - b * NSHIFT;
        const float* pp = g_partial + (size_t)b * BLK_PER_BATCH * NSHIFT + s;
        float acc = 0.0f;
#pragma unroll 8
        for (int i = 0; i < BLK_PER_BATCH; i++) acc += pp[i * NSHIFT];
        sims[t] = acc;
    }
    __syncthreads();

    int w = t >> 5, lane = t & 31;
    if (w < 4) {
        float bv = -3.0e38f;
        int bi = NSHIFT;
        for (int s = lane; s < NSHIFT; s += 32) {
            float v = sims[w * NSHIFT + s];
            if (v > bv || (v == bv && s < bi)) { bv = v; bi = s; }
        }
#pragma unroll
        for (int off = 16; off; off >>= 1) {
            float ov = __shfl_xor_sync(0xffffffffu, bv, off);
            int   oi = __shfl_xor_sync(0xffffffffu, bi, off);
            if (ov > bv || (ov == bv && oi < bi)) { bv = ov; bi = oi; }
        }
        if (lane == 0) {
            int sx = bi / 9 - 4;
            int sy = bi % 9 - 4;
            g_best[w] = make_int2(sx, sy);
            if (out_size >= OUT_IMG + 8) {
                d_out[OUT_IMG + w * 2 + 0] = (float)sx;
                d_out[OUT_IMG + w * 2 + 1] = (float)sy;
            }
        }
    }
}

// ---------------------------------------------------------------------------
// Phase 3: apply best shift. 4 floats per thread: 2 aligned LDG.128 +
// warp-uniform extract -> 1 STG.128.  (Best measured variant.)
// ---------------------------------------------------------------------------
__global__ void __launch_bounds__(256) apply_kernel(const float* __restrict__ x,
                                                    float* __restrict__ out) {
    int t = blockIdx.x * 256 + threadIdx.x;      // float4 index
    int base = t << 2;
    int j0  = base & 511;
    int i   = (base >> 9) & 511;
    int img = base >> 18;
    int b   = img / 3;
    int2 s  = g_best[b];
    int si  = i - s.x;
    float4 v = make_float4(0.f, 0.f, 0.f, 0.f);
    if ((unsigned)si < (unsigned)HH) {
        int sj  = j0 - s.y;
        int sa  = sj & ~3;
        int off = sj & 3;                        // warp-uniform
        const float* row = x + ((size_t)img << 18) + (si << 9);
        float4 qa = ((unsigned)sa < (unsigned)WW)
                        ? __ldg((const float4*)(row + sa)) : v;
        float4 qb = ((unsigned)(sa + 4) < (unsigned)WW)
                        ? __ldg((const float4*)(row + sa + 4)) : v;
        switch (off) {
            case 0:  v = qa; break;
            case 1:  v = make_float4(qa.y, qa.z, qa.w, qb.x); break;
            case 2:  v = make_float4(qa.z, qa.w, qb.x, qb.y); break;
            default: v = make_float4(qa.w, qb.x, qb.y, qb.z); break;
        }
    }
    ((float4*)out)[t] = v;
}

// ---------------------------------------------------------------------------
extern "C" void kernel_launch(void* const* d_in, const int* in_sizes, int n_in,
                              void* d_out, int out_size) {
    const float* x_ref = (const float*)d_in[0];
    const float* x     = (const float*)d_in[1];
    float* out = (float*)d_out;

    {
        int total4 = NIMG * PROWS * PADW4;
        prep_kernel<<<(total4 + 255) / 256, 256>>>(x_ref);
    }
    corr_kernel<<<NBLK, 256>>>(x);
    reduce_argmax_kernel<<<1, 384>>>(out, out_size);
    apply_kernel<<<OUT_IMG / 4 / 256, 256>>>(x, out);
}

// round 14
// speedup vs baseline: 1.4639x; 1.0299x over previous
#include <cuda_runtime.h>

// x_ref, x : [B=4, C=3, H=512, W=512] float32
// out: [4,3,512,512] f32 (3145728) then best_shifts [4,2] as floats (8)

#define NIMG   12
#define HH     512
#define WW     512
#define W4     (WW/4)        // 128
#define NSHIFT 81
#define IMG_ELEMS (HH*WW)
#define OUT_IMG   (NIMG*IMG_ELEMS)
#define NBLK   768           // 12 imgs * 64 blocks (8 rows per block)
#define BLK_PER_BATCH 192    // 3 imgs * 64
#define TROWS  16            // 8 tile rows + 4 halo each side
#define TCOLS4 130           // 520 padded cols / 4, stored even/odd split

__device__ float g_partial[NBLK * NSHIFT];
__device__ int2  g_best[4];

// even/odd split slot for colblock c (0..129): even -> 0..64, odd -> 65..129
__device__ __forceinline__ int eo_slot(int c) {
    return (c & 1) ? (65 + (c >> 1)) : (c >> 1);
}

// ---------------------------------------------------------------------------
// Phase 1: 81-shift correlation. Ref tile staged in smem (zero-padded halo,
// even/odd split -> hot-loop LDS.128 are 16B-lane-stride conflict-free).
// Thread: 4 rows x 8 cols; dx-outer; ref-ordered inner loop (no rv window
// live range) -> ~57 live regs, default 64-reg alloc, no spills.
// Block = 128 thr = 2 rowgroups(4 rows) x 64 strips; 6 CTAs/SM = 24 warps.
// ---------------------------------------------------------------------------
__global__ void __launch_bounds__(128) corr_kernel(const float* __restrict__ x,
                                                   const float* __restrict__ xref) {
    __shared__ float4 tile[TROWS * TCOLS4];   // 33280 B
    __shared__ float  ssum[NSHIFT];

    int t = threadIdx.x;
    if (t < NSHIFT) ssum[t] = 0.0f;

    int img      = blockIdx.x >> 6;           // 64 blocks per image
    int rowblk   = blockIdx.x & 63;
    int rowstart = rowblk * 8;

    // ---- stage zero-padded ref tile: rows [rowstart-4, rowstart+12),
    //      colblocks 0..129 (image colblocks -1..128), even/odd split ----
    {
        int tc = t & 31, tr = t >> 5;         // 4 row-workers x 32 col-workers
        const float* refimg = xref + ((size_t)img << 18);
#pragma unroll
        for (int pr = tr; pr < TROWS; pr += 4) {
            int grow = rowstart + pr - 4;
            bool rok = (unsigned)grow < (unsigned)HH;
            const float4* src = (const float4*)(refimg + ((size_t)(grow & 511) << 9));
            float4* drow = tile + pr * TCOLS4;
#pragma unroll
            for (int pc4 = tc; pc4 < TCOLS4; pc4 += 32) {
                float4 v = make_float4(0.f, 0.f, 0.f, 0.f);
                if (rok && pc4 >= 1 && pc4 <= 128) v = __ldg(src + (pc4 - 1));
                drow[eo_slot(pc4)] = v;
            }
        }
    }
    __syncthreads();

    int strip = t & 63;                       // 8-col strip
    int rgrp  = t >> 6;                       // 0..1
    int lr0   = rgrp * 4;                     // local tile row of first x row
    int a0    = rowstart + lr0;               // image row of first x row
    int lane  = t & 31;

    // preload x strip: 4 rows x 8 cols (32 regs)
    const float4* xp4 = (const float4*)x + ((size_t)img << 16);
    float xv[32];
#pragma unroll
    for (int r = 0; r < 4; r++) {
        float4 m0 = __ldg(xp4 + (a0 + r) * W4 + strip * 2);
        float4 m1 = __ldg(xp4 + (a0 + r) * W4 + strip * 2 + 1);
        xv[r * 8 + 0] = m0.x; xv[r * 8 + 1] = m0.y;
        xv[r * 8 + 2] = m0.z; xv[r * 8 + 3] = m0.w;
        xv[r * 8 + 4] = m1.x; xv[r * 8 + 5] = m1.y;
        xv[r * 8 + 6] = m1.z; xv[r * 8 + 7] = m1.w;
    }

    const float4* trow0 = tile + lr0 * TCOLS4;

#pragma unroll 1
    for (int dx = 0; dx < 9; dx++) {
        float acc[9];
#pragma unroll
        for (int d = 0; d < 9; d++) acc[d] = 0.0f;

#pragma unroll
        for (int r = 0; r < 4; r++) {
            const float4* rp = trow0 + (r + dx) * TCOLS4;
            // window colblocks 2s..2s+3 (16 ref floats), conflict-free LDS.128
            float4 e0 = rp[strip];            // colblock 2s     -> k 0..3
            float4 o0 = rp[65 + strip];       // colblock 2s+1   -> k 4..7
            float4 e1 = rp[strip + 1];        // colblock 2s+2   -> k 8..11
            float4 o1 = rp[66 + strip];       // colblock 2s+3   -> k 12..15
            float rv[16] = {e0.x, e0.y, e0.z, e0.w, o0.x, o0.y, o0.z, o0.w,
                            e1.x, e1.y, e1.z, e1.w, o1.x, o1.y, o1.z, o1.w};
            // ref-ordered: consume each rv[k] immediately (liveness dies fast)
#pragma unroll
            for (int k = 0; k < 16; k++) {
                const int dlo = (k - 7 < 0) ? 0 : k - 7;
                const int dhi = (k < 8) ? k : 8;
#pragma unroll
                for (int d = dlo; d <= dhi; d++) {
                    acc[d] += xv[r * 8 + (k - d)] * rv[k];
                }
            }
        }

        // warp butterfly per dy, then one-lane atomic into block smem
#pragma unroll
        for (int d = 0; d < 9; d++) {
            float v = acc[d];
            v += __shfl_xor_sync(0xffffffffu, v, 16);
            v += __shfl_xor_sync(0xffffffffu, v, 8);
            v += __shfl_xor_sync(0xffffffffu, v, 4);
            v += __shfl_xor_sync(0xffffffffu, v, 2);
            v += __shfl_xor_sync(0xffffffffu, v, 1);
            int s = dx * 9 + d;
            if (lane == (s & 31)) atomicAdd(&ssum[s], v);
        }
    }

    __syncthreads();
    if (t < NSHIFT)
        g_partial[blockIdx.x * NSHIFT + t] = ssum[t];
}

// ---------------------------------------------------------------------------
// Phase 2: deterministic reduce of 192 partials per (batch,shift) + argmax
// (first-max tie-break, matching jnp.argmax).
// ---------------------------------------------------------------------------
__global__ void __launch_bounds__(384) reduce_argmax_kernel(float* __restrict__ d_out,
                                                            int out_size) {
    __shared__ float sims[4 * NSHIFT];
    int t = threadIdx.x;
    if (t < 4 * NSHIFT) {
        int b = t / NSHIFT;
        int s = t - b * NSHIFT;
        const float* pp = g_partial + (size_t)b * BLK_PER_BATCH * NSHIFT + s;
        float acc = 0.0f;
#pragma unroll 8
        for (int i = 0; i < BLK_PER_BATCH; i++) acc += pp[i * NSHIFT];
        sims[t] = acc;
    }
    __syncthreads();

    int w = t >> 5, lane = t & 31;
    if (w < 4) {
        float bv = -3.0e38f;
        int bi = NSHIFT;
        for (int s = lane; s < NSHIFT; s += 32) {
            float v = sims[w * NSHIFT + s];
            if (v > bv || (v == bv && s < bi)) { bv = v; bi = s; }
        }
#pragma unroll
        for (int off = 16; off; off >>= 1) {
            float ov = __shfl_xor_sync(0xffffffffu, bv, off);
            int   oi = __shfl_xor_sync(0xffffffffu, bi, off);
            if (ov > bv || (ov == bv && oi < bi)) { bv = ov; bi = oi; }
        }
        if (lane == 0) {
            int sx = bi / 9 - 4;
            int sy = bi % 9 - 4;
            g_best[w] = make_int2(sx, sy);
            if (out_size >= OUT_IMG + 8) {
                d_out[OUT_IMG + w * 2 + 0] = (float)sx;
                d_out[OUT_IMG + w * 2 + 1] = (float)sy;
            }
        }
    }
}

// ---------------------------------------------------------------------------
// Phase 3: apply best shift. 4 floats per thread: 2 aligned LDG.128 +
// warp-uniform extract -> 1 STG.128.  (Best measured variant: 7.5-7.8 us.)
// ---------------------------------------------------------------------------
__global__ void __launch_bounds__(256) apply_kernel(const float* __restrict__ x,
                                                    float* __restrict__ out) {
    int t = blockIdx.x * 256 + threadIdx.x;      // float4 index
    int base = t << 2;
    int j0  = base & 511;
    int i   = (base >> 9) & 511;
    int img = base >> 18;
    int b   = img / 3;
    int2 s  = g_best[b];
    int si  = i - s.x;
    float4 v = make_float4(0.f, 0.f, 0.f, 0.f);
    if ((unsigned)si < (unsigned)HH) {
        int sj  = j0 - s.y;
        int sa  = sj & ~3;
        int off = sj & 3;                        // warp-uniform
        const float* row = x + ((size_t)img << 18) + (si << 9);
        float4 qa = ((unsigned)sa < (unsigned)WW)
                        ? __ldg((const float4*)(row + sa)) : v;
        float4 qb = ((unsigned)(sa + 4) < (unsigned)WW)
                        ? __ldg((const float4*)(row + sa + 4)) : v;
        switch (off) {
            case 0:  v = qa; break;
            case 1:  v = make_float4(qa.y, qa.z, qa.w, qb.x); break;
            case 2:  v = make_float4(qa.z, qa.w, qb.x, qb.y); break;
            default: v = make_float4(qa.w, qb.x, qb.y, qb.z); break;
        }
    }
    ((float4*)out)[t] = v;
}

// ---------------------------------------------------------------------------
extern "C" void kernel_launch(void* const* d_in, const int* in_sizes, int n_in,
                              void* d_out, int out_size) {
    const float* x_ref = (const float*)d_in[0];
    const float* x     = (const float*)d_in[1];
    float* out = (float*)d_out;

    corr_kernel<<<NBLK, 128>>>(x, x_ref);
    reduce_argmax_kernel<<<1, 384>>>(out, out_size);
    apply_kernel<<<OUT_IMG / 4 / 256, 256>>>(x, out);
}

// round 15
// speedup vs baseline: 1.5510x; 1.0595x over previous
#include <cuda_runtime.h>

// x_ref, x : [B=4, C=3, H=512, W=512] float32
// out: [4,3,512,512] f32 (3145728) then best_shifts [4,2] as floats (8)

#define NIMG   12
#define HH     512
#define WW     512
#define W4     (WW/4)
#define PROWS  520          // 4-row halo each side
#define PADW   520          // 4-col halo each side
#define PADW4  (PADW/4)     // 130
#define NSHIFT 81
#define IMG_ELEMS (HH*WW)
#define OUT_IMG   (NIMG*IMG_ELEMS)
#define NROWBLK 384         // 12 imgs * 32 row-blocks
#define NDXG    3           // dx groups of 3
#define NBLK    (NROWBLK*NDXG)   // 1152
#define BLK_PER_BATCH 96    // 3 imgs * 32 row-blocks (g_partial rows per batch)

__device__ float4 g_refpad[NIMG * PROWS * PADW4];   // ~13 MB zero-padded ref
__device__ float  g_partial[NROWBLK * NSHIFT];
__device__ int2   g_best[4];

// ---------------------------------------------------------------------------
// Phase 0: zero-padded ref copy, one aligned float4 per thread (DRAM-bound).
// ---------------------------------------------------------------------------
__global__ void __launch_bounds__(256) prep_kernel(const float* __restrict__ xref) {
    int idx = blockIdx.x * 256 + threadIdx.x;
    const int total4 = NIMG * PROWS * PADW4;     // 811200
    if (idx >= total4) return;
    int pc4 = idx % PADW4;
    int pr  = (idx / PADW4) % PROWS;
    int img = idx / (PADW4 * PROWS);
    int srow = pr - 4;
    float4 v = make_float4(0.f, 0.f, 0.f, 0.f);
    if ((unsigned)srow < (unsigned)HH && pc4 >= 1 && pc4 <= 128) {
        v = __ldg((const float4*)(xref + ((size_t)img * HH + srow) * WW) + (pc4 - 1));
    }
    g_refpad[idx] = v;
}

// ---------------------------------------------------------------------------
// Phase 1: 81-shift correlation, R4 hot loop, dx-split across 3 block groups.
// Thread: 4 rows x 8 cols; 3 dx values; 9 live accumulators; 864 FMAs/thread.
// Block = 256 thr = 4 rowgroups x 64 strips; grid = 384 rowblocks x 3 dxgroups
// -> ~7.8 CTAs/SM (4 resident at 64 regs) = 32 warps: latency finally hidden.
// ---------------------------------------------------------------------------
__global__ void __launch_bounds__(256) corr_kernel(const float* __restrict__ x) {
    __shared__ float ssum[NSHIFT];
    if (threadIdx.x < NSHIFT) ssum[threadIdx.x] = 0.0f;
    __syncthreads();

    int b384  = blockIdx.x % NROWBLK;            // row-block id
    int dxg   = blockIdx.x / NROWBLK;            // 0..2 -> dx in [3*dxg, 3*dxg+3)
    int img   = b384 >> 5;
    int strip = threadIdx.x & 63;
    int rgrp  = ((b384 & 31) << 2) + (threadIdx.x >> 6);
    int a0    = rgrp * 4;
    int lane  = threadIdx.x & 31;

    // preload x strip: 4 rows x 8 cols (32 regs)
    const float4* xp4 = (const float4*)x + (size_t)img * HH * W4;
    float xv[32];
#pragma unroll
    for (int r = 0; r < 4; r++) {
        float4 m0 = __ldg(xp4 + (a0 + r) * W4 + strip * 2);
        float4 m1 = __ldg(xp4 + (a0 + r) * W4 + strip * 2 + 1);
        xv[r * 8 + 0] = m0.x; xv[r * 8 + 1] = m0.y;
        xv[r * 8 + 2] = m0.z; xv[r * 8 + 3] = m0.w;
        xv[r * 8 + 4] = m1.x; xv[r * 8 + 5] = m1.y;
        xv[r * 8 + 6] = m1.z; xv[r * 8 + 7] = m1.w;
    }

    // running row pointer: first dx of this group touches padded row a0+3*dxg
    const float4* rrow = g_refpad + (size_t)img * PROWS * PADW4
                         + (size_t)(a0 + 3 * dxg) * PADW4 + strip * 2;

#pragma unroll 1
    for (int dxi = 0; dxi < 3; dxi++) {
        int dx = dxg * 3 + dxi;
        float acc[9];
#pragma unroll
        for (int d = 0; d < 9; d++) acc[d] = 0.0f;

#pragma unroll
        for (int r = 0; r < 4; r++) {
            const float4* rp = rrow + r * PADW4;
            float4 q0 = rp[0], q1 = rp[1], q2 = rp[2], q3 = rp[3];
            float rv[16] = {q0.x, q0.y, q0.z, q0.w, q1.x, q1.y, q1.z, q1.w,
                            q2.x, q2.y, q2.z, q2.w, q3.x, q3.y, q3.z, q3.w};
#pragma unroll
            for (int p = 0; p < 8; p++) {
#pragma unroll
                for (int d = 0; d < 9; d++) {
                    acc[d] += xv[r * 8 + p] * rv[p + d];
                }
            }
        }

        // warp butterfly per dy, then one-lane atomic into block smem
#pragma unroll
        for (int d = 0; d < 9; d++) {
            float v = acc[d];
            v += __shfl_xor_sync(0xffffffffu, v, 16);
            v += __shfl_xor_sync(0xffffffffu, v, 8);
            v += __shfl_xor_sync(0xffffffffu, v, 4);
            v += __shfl_xor_sync(0xffffffffu, v, 2);
            v += __shfl_xor_sync(0xffffffffu, v, 1);
            int s = dx * 9 + d;
            if (lane == (s & 31)) atomicAdd(&ssum[s], v);
        }
        rrow += PADW4;
    }

    __syncthreads();
    // write only this dx-group's 27 shifts; the 3 groups of a row-block
    // fill disjoint slices of the same g_partial row (deterministic).
    int t = threadIdx.x;
    int s0 = dxg * 27;
    if (t >= s0 && t < s0 + 27)
        g_partial[b384 * NSHIFT + t] = ssum[t];
}

// ---------------------------------------------------------------------------
// Phase 2: deterministic reduce of 96 partials per (batch,shift) + argmax
// (first-max tie-break, matching jnp.argmax).
// ---------------------------------------------------------------------------
__global__ void __launch_bounds__(384) reduce_argmax_kernel(float* __restrict__ d_out,
                                                            int out_size) {
    __shared__ float sims[4 * NSHIFT];
    int t = threadIdx.x;
    if (t < 4 * NSHIFT) {
        int b = t / NSHIFT;
        int s = t - b * NSHIFT;
        const float* pp = g_partial + (size_t)b * BLK_PER_BATCH * NSHIFT + s;
        float acc = 0.0f;
#pragma unroll 8
        for (int i = 0; i < BLK_PER_BATCH; i++) acc += pp[i * NSHIFT];
        sims[t] = acc;
    }
    __syncthreads();

    int w = t >> 5, lane = t & 31;
    if (w < 4) {
        float bv = -3.0e38f;
        int bi = NSHIFT;
        for (int s = lane; s < NSHIFT; s += 32) {
            float v = sims[w * NSHIFT + s];
            if (v > bv || (v == bv && s < bi)) { bv = v; bi = s; }
        }
#pragma unroll
        for (int off = 16; off; off >>= 1) {
            float ov = __shfl_xor_sync(0xffffffffu, bv, off);
            int   oi = __shfl_xor_sync(0xffffffffu, bi, off);
            if (ov > bv || (ov == bv && oi < bi)) { bv = ov; bi = oi; }
        }
        if (lane == 0) {
            int sx = bi / 9 - 4;
            int sy = bi % 9 - 4;
            g_best[w] = make_int2(sx, sy);
            if (out_size >= OUT_IMG + 8) {
                d_out[OUT_IMG + w * 2 + 0] = (float)sx;
                d_out[OUT_IMG + w * 2 + 1] = (float)sy;
            }
        }
    }
}

// ---------------------------------------------------------------------------
// Phase 3: apply best shift. 4 floats per thread: 2 aligned LDG.128 +
// warp-uniform extract -> 1 STG.128.  (Best measured variant.)
// ---------------------------------------------------------------------------
__global__ void __launch_bounds__(256) apply_kernel(const float* __restrict__ x,
                                                    float* __restrict__ out) {
    int t = blockIdx.x * 256 + threadIdx.x;      // float4 index
    int base = t << 2;
    int j0  = base & 511;
    int i   = (base >> 9) & 511;
    int img = base >> 18;
    int b   = img / 3;
    int2 s  = g_best[b];
    int si  = i - s.x;
    float4 v = make_float4(0.f, 0.f, 0.f, 0.f);
    if ((unsigned)si < (unsigned)HH) {
        int sj  = j0 - s.y;
        int sa  = sj & ~3;
        int off = sj & 3;                        // warp-uniform
        const float* row = x + ((size_t)img << 18) + (si << 9);
        float4 qa = ((unsigned)sa < (unsigned)WW)
                        ? __ldg((const float4*)(row + sa)) : v;
        float4 qb = ((unsigned)(sa + 4) < (unsigned)WW)
                        ? __ldg((const float4*)(row + sa + 4)) : v;
        switch (off) {
            case 0:  v = qa; break;
            case 1:  v = make_float4(qa.y, qa.z, qa.w, qb.x); break;
            case 2:  v = make_float4(qa.z, qa.w, qb.x, qb.y); break;
            default: v = make_float4(qa.w, qb.x, qb.y, qb.z); break;
        }
    }
    ((float4*)out)[t] = v;
}

// ---------------------------------------------------------------------------
extern "C" void kernel_launch(void* const* d_in, const int* in_sizes, int n_in,
                              void* d_out, int out_size) {
    const float* x_ref = (const float*)d_in[0];
    const float* x     = (const float*)d_in[1];
    float* out = (float*)d_out;

    {
        int total4 = NIMG * PROWS * PADW4;
        prep_kernel<<<(total4 + 255) / 256, 256>>>(x_ref);
    }
    corr_kernel<<<NBLK, 256>>>(x);
    reduce_argmax_kernel<<<1, 384>>>(out, out_size);
    apply_kernel<<<OUT_IMG / 4 / 256, 256>>>(x, out);
}

// round 16
// speedup vs baseline: 1.6304x; 1.0512x over previous
#include <cuda_runtime.h>

// x_ref, x : [B=4, C=3, H=512, W=512] float32
// out: [4,3,512,512] f32 (3145728) then best_shifts [4,2] as floats (8)

#define NIMG   12
#define HH     512
#define WW     512
#define W4     (WW/4)
#define NSHIFT 81
#define IMG_ELEMS (HH*WW)
#define OUT_IMG   (NIMG*IMG_ELEMS)
#define NROWBLK 384         // 12 imgs * 32 row-blocks (16 rows each)
#define NBLK    (NROWBLK*9) // one dx per block
#define BLK_PER_BATCH 96    // 3 imgs * 32 row-blocks per batch

__device__ float g_partial[NROWBLK * NSHIFT];
__device__ int2  g_best[4];

// ---------------------------------------------------------------------------
// Phase 1: 81-shift correlation; ONE dx per block (straight-line body).
// Thread: 4 rows x 8 cols; 9 accumulators; 288 FMAs; ref read directly from
// x_ref with warp-uniform row predicate + edge-strip col predicates.
// Ref-ordered inner loop: loaded ref values die immediately (~60 live regs).
// Block = 256 thr = 4 rowgroups x 64 strips. Grid = 384 rowblocks x 9 dx.
// Reduction: warp butterfly -> wsum[8][9] -> fixed-order sum (deterministic).
// ---------------------------------------------------------------------------
__global__ void __launch_bounds__(256) corr_kernel(const float* __restrict__ x,
                                                   const float* __restrict__ xref) {
    __shared__ float wsum[8][9];

    int t    = threadIdx.x;
    int b384 = blockIdx.x % NROWBLK;             // row-block id
    int dx   = blockIdx.x / NROWBLK;             // 0..8
    int img  = b384 >> 5;
    int strip= t & 63;
    int rgrp = ((b384 & 31) << 2) + (t >> 6);
    int a0   = rgrp * 4;
    int lane = t & 31;
    int wid  = t >> 5;

    // preload x strip: 4 rows x 8 cols (32 regs)
    const float4* xp4 = (const float4*)x + ((size_t)img << 16);
    float xv[32];
#pragma unroll
    for (int r = 0; r < 4; r++) {
        float4 m0 = __ldg(xp4 + (a0 + r) * W4 + strip * 2);
        float4 m1 = __ldg(xp4 + (a0 + r) * W4 + strip * 2 + 1);
        xv[r * 8 + 0] = m0.x; xv[r * 8 + 1] = m0.y;
        xv[r * 8 + 2] = m0.z; xv[r * 8 + 3] = m0.w;
        xv[r * 8 + 4] = m1.x; xv[r * 8 + 5] = m1.y;
        xv[r * 8 + 6] = m1.z; xv[r * 8 + 7] = m1.w;
    }

    float acc[9];
#pragma unroll
    for (int d = 0; d < 9; d++) acc[d] = 0.0f;

    const bool leftok  = (strip != 0);
    const bool rightok = (strip != 63);
    const float4 z4 = make_float4(0.f, 0.f, 0.f, 0.f);
    const float4* ref4 = (const float4*)xref + ((size_t)img << 16);

#pragma unroll
    for (int r = 0; r < 4; r++) {
        int ar = a0 + r + dx - 4;                 // warp-uniform ref row
        bool rok = (unsigned)ar < (unsigned)HH;
        const float4* rp = ref4 + ar * W4 + strip * 2 - 1;   // col j0-4
        float4 q0 = (rok && leftok)  ? __ldg(rp + 0) : z4;   // k 0..3
        float4 q1 =  rok             ? __ldg(rp + 1) : z4;   // k 4..7
        float4 q2 =  rok             ? __ldg(rp + 2) : z4;   // k 8..11
        float4 q3 = (rok && rightok) ? __ldg(rp + 3) : z4;   // k 12..15
        float rv[16] = {q0.x, q0.y, q0.z, q0.w, q1.x, q1.y, q1.z, q1.w,
                        q2.x, q2.y, q2.z, q2.w, q3.x, q3.y, q3.z, q3.w};
        // ref-ordered: consume rv[k] immediately; acc[d] += xv[k-d]*rv[k]
#pragma unroll
        for (int k = 0; k < 16; k++) {
            const int dlo = (k - 7 < 0) ? 0 : k - 7;
            const int dhi = (k < 8) ? k : 8;
#pragma unroll
            for (int d = dlo; d <= dhi; d++) {
                acc[d] += xv[r * 8 + (k - d)] * rv[k];
            }
        }
    }

    // warp butterfly per dy; lane d stores warp-total of acc[d]
#pragma unroll
    for (int d = 0; d < 9; d++) {
        float v = acc[d];
        v += __shfl_xor_sync(0xffffffffu, v, 16);
        v += __shfl_xor_sync(0xffffffffu, v, 8);
        v += __shfl_xor_sync(0xffffffffu, v, 4);
        v += __shfl_xor_sync(0xffffffffu, v, 2);
        v += __shfl_xor_sync(0xffffffffu, v, 1);
        if (lane == d) wsum[wid][d] = v;
    }
    __syncthreads();

    // deterministic fixed-order sum over the 8 warps, write 9-shift slice
    if (t < 9) {
        float s = 0.0f;
#pragma unroll
        for (int w = 0; w < 8; w++) s += wsum[w][t];
        g_partial[b384 * NSHIFT + dx * 9 + t] = s;
    }
}

// ---------------------------------------------------------------------------
// Phase 2: deterministic reduce of 96 partials per (batch,shift) + argmax
// (first-max tie-break, matching jnp.argmax).
// ---------------------------------------------------------------------------
__global__ void __launch_bounds__(384) reduce_argmax_kernel(float* __restrict__ d_out,
                                                            int out_size) {
    __shared__ float sims[4 * NSHIFT];
    int t = threadIdx.x;
    if (t < 4 * NSHIFT) {
        int b = t / NSHIFT;
        int s = t - b * NSHIFT;
        const float* pp = g_partial + (size_t)b * BLK_PER_BATCH * NSHIFT + s;
        float acc = 0.0f;
#pragma unroll 8
        for (int i = 0; i < BLK_PER_BATCH; i++) acc += pp[i * NSHIFT];
        sims[t] = acc;
    }
    __syncthreads();

    int w = t >> 5, lane = t & 31;
    if (w < 4) {
        float bv = -3.0e38f;
        int bi = NSHIFT;
        for (int s = lane; s < NSHIFT; s += 32) {
            float v = sims[w * NSHIFT + s];
            if (v > bv || (v == bv && s < bi)) { bv = v; bi = s; }
        }
#pragma unroll
        for (int off = 16; off; off >>= 1) {
            float ov = __shfl_xor_sync(0xffffffffu, bv, off);
            int   oi = __shfl_xor_sync(0xffffffffu, bi, off);
            if (ov > bv || (ov == bv && oi < bi)) { bv = ov; bi = oi; }
        }
        if (lane == 0) {
            int sx = bi / 9 - 4;
            int sy = bi % 9 - 4;
            g_best[w] = make_int2(sx, sy);
            if (out_size >= OUT_IMG + 8) {
                d_out[OUT_IMG + w * 2 + 0] = (float)sx;
                d_out[OUT_IMG + w * 2 + 1] = (float)sy;
            }
        }
    }
}

// ---------------------------------------------------------------------------
// Phase 3: apply best shift. 4 floats per thread: 2 aligned LDG.128 +
// warp-uniform extract -> 1 STG.128.  (Best measured variant.)
// ---------------------------------------------------------------------------
__global__ void __launch_bounds__(256) apply_kernel(const float* __restrict__ x,
                                                    float* __restrict__ out) {
    int t = blockIdx.x * 256 + threadIdx.x;      // float4 index
    int base = t << 2;
    int j0  = base & 511;
    int i   = (base >> 9) & 511;
    int img = base >> 18;
    int b   = img / 3;
    int2 s  = g_best[b];
    int si  = i - s.x;
    float4 v = make_float4(0.f, 0.f, 0.f, 0.f);
    if ((unsigned)si < (unsigned)HH) {
        int sj  = j0 - s.y;
        int sa  = sj & ~3;
        int off = sj & 3;                        // warp-uniform
        const float* row = x + ((size_t)img << 18) + (si << 9);
        float4 qa = ((unsigned)sa < (unsigned)WW)
                        ? __ldg((const float4*)(row + sa)) : v;
        float4 qb = ((unsigned)(sa + 4) < (unsigned)WW)
                        ? __ldg((const float4*)(row + sa + 4)) : v;
        switch (off) {
            case 0:  v = qa; break;
            case 1:  v = make_float4(qa.y, qa.z, qa.w, qb.x); break;
            case 2:  v = make_float4(qa.z, qa.w, qb.x, qb.y); break;
            default: v = make_float4(qa.w, qb.x, qb.y, qb.z); break;
        }
    }
    ((float4*)out)[t] = v;
}

// ---------------------------------------------------------------------------
extern "C" void kernel_launch(void* const* d_in, const int* in_sizes, int n_in,
                              void* d_out, int out_size) {
    const float* x_ref = (const float*)d_in[0];
    const float* x     = (const float*)d_in[1];
    float* out = (float*)d_out;

    corr_kernel<<<NBLK, 256>>>(x, x_ref);
    reduce_argmax_kernel<<<1, 384>>>(out, out_size);
    apply_kernel<<<OUT_IMG / 4 / 256, 256>>>(x, out);
}